// round 6
// baseline (speedup 1.0000x reference)
#include <cuda_runtime.h>
#include <cstdint>
#include <cstddef>

#define Bn 16
#define Cn 256
#define Hn 64
#define Wn 64
#define MAXD 4
#define PP 81
#define HW (Hn * Wn)

#define TILE_I 8
#define CC 8
#define NCHUNK (Cn / CC)        // 32
#define YROWS 10                // TILE_I + 2 (3 di per pass)
#define YCOLS 72                // 64 + 2*4 halo
#define NT 128
#define TPR 16                  // threads per pixel row (4 cols each)

#define SY_FLOATS (CC * YROWS * YCOLS)   // 5760
#define SY_BYTES  (SY_FLOATS * 4)        // 23040
#define SMEM_TOTAL (2 * SY_BYTES)        // 46080

typedef unsigned long long ull;

__device__ __forceinline__ ull pack2(float lo, float hi) {
    ull r;
    asm("mov.b64 %0, {%1, %2};" : "=l"(r) : "f"(lo), "f"(hi));
    return r;
}
__device__ __forceinline__ ull fma2(ull a, ull b, ull c) {
    ull d;
    asm("fma.rn.f32x2 %0, %1, %2, %3;" : "=l"(d) : "l"(a), "l"(b), "l"(c));
    return d;
}
__device__ __forceinline__ void unpack2(ull v, float& lo, float& hi) {
    asm("mov.b64 {%0, %1}, %2;" : "=f"(lo), "=f"(hi) : "l"(v));
}

__device__ __forceinline__ void cp16(uint32_t dst, const void* src) {
    asm volatile("cp.async.cg.shared.global [%0], [%1], 16;\n"
                 :: "r"(dst), "l"(src));
}
__device__ __forceinline__ void cp_commit() {
    asm volatile("cp.async.commit_group;\n" ::: "memory");
}
__device__ __forceinline__ void cp_wait1() {
    asm volatile("cp.async.wait_group 1;\n" ::: "memory");
}
__device__ __forceinline__ void cp_wait0() {
    asm volatile("cp.async.wait_group 0;\n" ::: "memory");
}

__global__ __launch_bounds__(NT, 3)
void corr_kernel(const float* __restrict__ x,
                 const float* __restrict__ y,
                 float* __restrict__ out)
{
    extern __shared__ float smem[];

    const int tid = threadIdx.x;
    const int tc  = tid & (TPR - 1);    // pixel cols 4tc .. 4tc+3
    const int tr  = tid >> 4;           // pixel row in tile, 0..7
    const int i0  = blockIdx.x * TILE_I;
    const int b   = blockIdx.y;
    const int d0  = blockIdx.z * 3;     // di in {d0, d0+1, d0+2}
    const int yrow0 = i0 + d0 - MAXD;   // global row for sy row 0

    const float* xb = x + (size_t)b * Cn * HW;
    const float* yb = y + (size_t)b * Cn * HW;
    const uint32_t sbase = (uint32_t)__cvta_generic_to_shared(smem);

    // ---- zero both y buffers once (halo cols + OOB rows stay zero forever) ----
    {
        float4* s4 = (float4*)smem;
        #pragma unroll
        for (int i = 0; i < SMEM_TOTAL / 16 / NT + 1; i++) {
            int idx = tid + i * NT;
            if (idx < SMEM_TOTAL / 16)
                s4[idx] = make_float4(0.f, 0.f, 0.f, 0.f);
        }
    }
    __syncthreads();

    ull acc[3][9][2];
    #pragma unroll
    for (int dl = 0; dl < 3; dl++)
        #pragma unroll
        for (int dj = 0; dj < 9; dj++) {
            acc[dl][dj][0] = 0ull;      // packed (0.0f, 0.0f)
            acc[dl][dj][1] = 0ull;
        }

    // ---- issue chunk k's y loads into buffer (k&1) ----
    // SY data region per chunk: 8cc x 10rows x 16 float4 = 1280 float4 -> 10/thread
    auto issue = [&](int k) {
        const uint32_t syb = sbase + (uint32_t)(k & 1) * SY_BYTES;
        const float* ybk = yb + (size_t)(k * CC) * HW;
        #pragma unroll
        for (int m = 0; m < 10; m++) {
            const int idx = tid + NT * m;       // 0..1279
            const int cc  = idx / 160;          // 160 = 10 rows * 16 quads
            const int rem = idx - cc * 160;
            const int r   = rem >> 4;
            const int q   = rem & 15;
            const int gr  = yrow0 + r;
            if ((unsigned)gr < (unsigned)Hn) {
                const float* src = ybk + (size_t)cc * HW + gr * Wn + q * 4;
                const uint32_t dst = syb +
                    (uint32_t)(((cc * YROWS + r) * YCOLS + 4 + q * 4) * 4);
                cp16(dst, src);
            }
        }
        cp_commit();
    };

    // x: direct LDG.128, one channel ahead
    const float* xrow = xb + (i0 + tr) * Wn + 4 * tc;
    float4 xv = *(const float4*)xrow;           // channel 0

    issue(0);
    #pragma unroll 1
    for (int k = 0; k < NCHUNK; k++) {
        if (k + 1 < NCHUNK) { issue(k + 1); cp_wait1(); }
        else                { cp_wait0(); }
        __syncthreads();

        const float* syt = smem + (k & 1) * SY_FLOATS + tr * YCOLS + 4 * tc;

        #pragma unroll 1
        for (int cc = 0; cc < CC; cc++) {
            const int ch = k * CC + cc;
            const int chn = (ch + 1 < Cn) ? (ch + 1) : ch;
            const float4 xn = *(const float4*)(xrow + (size_t)chn * HW);

            const ull xp0 = pack2(xv.x, xv.y);
            const ull xp1 = pack2(xv.z, xv.w);

            #pragma unroll
            for (int dl = 0; dl < 3; dl++) {
                const float4* yr = (const float4*)(syt + (cc * YROWS + dl) * YCOLS);
                const float4 a = yr[0];
                const float4 g = yr[1];
                const float4 h = yr[2];
                ull s[11];
                s[0]  = pack2(a.x, a.y);
                s[2]  = pack2(a.z, a.w);
                s[4]  = pack2(g.x, g.y);
                s[6]  = pack2(g.z, g.w);
                s[8]  = pack2(h.x, h.y);
                s[10] = pack2(h.z, h.w);
                s[1]  = pack2(a.y, a.z);
                s[3]  = pack2(a.w, g.x);
                s[5]  = pack2(g.y, g.z);
                s[7]  = pack2(g.w, h.x);
                s[9]  = pack2(h.y, h.z);
                #pragma unroll
                for (int dj = 0; dj < 9; dj++) {
                    acc[dl][dj][0] = fma2(xp0, s[dj],     acc[dl][dj][0]);
                    acc[dl][dj][1] = fma2(xp1, s[dj + 2], acc[dl][dj][1]);
                }
            }
            xv = xn;
        }
        __syncthreads();        // protect buffer (k&1) before issue(k+2)
    }

    // ---- epilogue: 27 float4 stores, each output element exactly once ----
    const float scale = 1.f / (float)Cn;
    const int row = i0 + tr;
    #pragma unroll
    for (int dl = 0; dl < 3; dl++)
        #pragma unroll
        for (int dj = 0; dj < 9; dj++) {
            const int p = (d0 + dl) * 9 + dj;
            float4 v;
            unpack2(acc[dl][dj][0], v.x, v.y);
            unpack2(acc[dl][dj][1], v.z, v.w);
            v.x *= scale; v.y *= scale; v.z *= scale; v.w *= scale;
            *(float4*)&out[(((size_t)b * PP + p) * Hn + row) * Wn + 4 * tc] = v;
        }
}

extern "C" void kernel_launch(void* const* d_in, const int* in_sizes, int n_in,
                              void* d_out, int out_size)
{
    const float* x = (const float*)d_in[0];
    const float* y = (const float*)d_in[1];
    float* out = (float*)d_out;

    cudaFuncSetAttribute(corr_kernel,
                         cudaFuncAttributeMaxDynamicSharedMemorySize,
                         SMEM_TOTAL);

    dim3 grid(Hn / TILE_I, Bn, 3);   // 8 x 16 x 3 = 384 blocks
    dim3 block(NT);
    corr_kernel<<<grid, block, SMEM_TOTAL>>>(x, y, out);
}